// round 3
// baseline (speedup 1.0000x reference)
#include <cuda_runtime.h>
#include <cstdint>

// Problem constants: B=16, S=4096, D=64, K=4096
#define D_DIM     64
#define K_CODES   4096
#define N_ROWS    65536               // B*S
#define ROWS_CTA  128
#define THREADS   256
#define CHUNK     256                 // codes per smem chunk
#define N_CHUNKS  (K_CODES / CHUNK)   // 16
#define N_BLOCKS  (N_ROWS / ROWS_CTA) // 512
#define NQ_ELEMS  (N_ROWS * D_DIM)    // 4194304

// Device-global scratch (no allocations allowed)
__device__ float  g_embT[D_DIM * K_CODES];   // transposed codebook [d][k]
__device__ float  g_ee[K_CODES];             // ||e_k||^2, serial fp32
__device__ double g_lossPart[N_BLOCKS];      // per-CTA loss partials

__device__ __forceinline__ uint32_t smem_u32(const void* p) {
    return (uint32_t)__cvta_generic_to_shared(p);
}

#define CP16(dst, src) \
    asm volatile("cp.async.cg.shared.global [%0], [%1], 16;" :: "r"(dst), "l"(src))

struct __align__(16) Smem {
    float  e[2][D_DIM * CHUNK];   // 131072 B : embT chunk [d][c], double buffered
    float  ee[2][CHUNK];          //   2048 B
    float2 zdup[ROWS_CTA * 65];   //  66560 B : (2z,2z) per (row,d), stride 65
    float  zz[ROWS_CTA];          //    512 B
    float  redV[ROWS_CTA * 16];   //   8192 B
    int    redI[ROWS_CTA * 16];   //   8192 B
    double lossBuf[ROWS_CTA];     //   1024 B
};                                // total 217600 B

// ---------------------------------------------------------------------------
// Prep: transpose codebook + ||e||^2 (serial fp32 chain)
// ---------------------------------------------------------------------------
__global__ void vq_prep(const float* __restrict__ emb) {
    int k = blockIdx.x * blockDim.x + threadIdx.x;
    if (k >= K_CODES) return;
    float s = 0.0f;
    for (int d = 0; d < D_DIM; ++d) {
        float v = __ldg(&emb[k * D_DIM + d]);
        g_embT[d * K_CODES + k] = v;
        s = __fadd_rn(s, __fmul_rn(v, v));
    }
    g_ee[k] = s;
}

// ---------------------------------------------------------------------------
// Main kernel
// ---------------------------------------------------------------------------
__device__ __forceinline__ void load_chunk(Smem& sm, int buf, int chunk, int tid) {
    // chunk tile: 64 d-rows x 256 floats = 4096 x 16B segments (64 segs/row)
    uint32_t eBase = smem_u32(&sm.e[buf][0]);
    #pragma unroll
    for (int it = 0; it < 16; ++it) {
        int i   = tid + it * THREADS;        // 0..4095
        int d   = i >> 6;                    // 0..63
        int seg = i & 63;                    // 0..63  (seg*4 floats)
        uint32_t dst = eBase + (uint32_t)(d * CHUNK + seg * 4) * 4u;
        const float* s = g_embT + d * K_CODES + chunk * CHUNK + seg * 4;
        CP16(dst, s);
    }
    if (tid < 64) {
        uint32_t dst = smem_u32(&sm.ee[buf][0]) + tid * 16;
        const float* s = g_ee + chunk * CHUNK + tid * 4;
        CP16(dst, s);
    }
    asm volatile("cp.async.commit_group;" ::: "memory");
}

__global__ void __launch_bounds__(THREADS, 1)
vq_main(const float* __restrict__ z, const float* __restrict__ emb,
        float* __restrict__ out)
{
    extern __shared__ unsigned char smraw[];
    Smem& sm = *reinterpret_cast<Smem*>(smraw);

    const int tid = threadIdx.x;
    const int tc  = tid & 15;     // code group 0..15
    const int tr  = tid >> 4;     // row group 0..15 (8 rows each)
    const int rowBase = blockIdx.x * ROWS_CTA;

    // ---- load z tile, store duplicated (2z,2z); 2z exact ----
    const float4* zg = reinterpret_cast<const float4*>(z + (size_t)rowBase * D_DIM);
    #pragma unroll
    for (int it = 0; it < 8; ++it) {
        int q = tid + it * THREADS;          // 0..2047 float4s
        float4 v = zg[q];
        int row = q >> 4;
        int c   = (q & 15) << 2;
        float2* p = &sm.zdup[row * 65 + c];
        p[0] = make_float2(v.x + v.x, v.x + v.x);
        p[1] = make_float2(v.y + v.y, v.y + v.y);
        p[2] = make_float2(v.z + v.z, v.z + v.z);
        p[3] = make_float2(v.w + v.w, v.w + v.w);
    }
    __syncthreads();

    // ---- zz per row: serial fl(s + fl(z*z)) ----
    if (tid < ROWS_CTA) {
        float s = 0.0f;
        const float2* zr = &sm.zdup[tid * 65];
        for (int d = 0; d < D_DIM; ++d) {
            float zv = 0.5f * zr[d].x;       // exact recovery of z
            s = __fadd_rn(s, __fmul_rn(zv, zv));
        }
        sm.zz[tid] = s;
    }
    __syncthreads();

    float rzz[8];
    #pragma unroll
    for (int i = 0; i < 8; ++i) rzz[i] = sm.zz[tr * 8 + i];

    float bestV[8];
    int   bestI[8];
    #pragma unroll
    for (int i = 0; i < 8; ++i) { bestV[i] = 3.402823466e38f; bestI[i] = 0; }

    load_chunk(sm, 0, 0, tid);
    asm volatile("cp.async.wait_group 0;" ::: "memory");
    __syncthreads();

    const float2* zrow = &sm.zdup[tr * 8 * 65];

    for (int c = 0; c < N_CHUNKS; ++c) {
        const int buf = c & 1;
        if (c + 1 < N_CHUNKS) load_chunk(sm, (c + 1) & 1, c + 1, tid);

        // acc[i][j] = serial fma chain over d of (2z)*e, packed f32x2
        unsigned long long acc[8][8];
        #pragma unroll
        for (int i = 0; i < 8; ++i)
            #pragma unroll
            for (int j = 0; j < 8; ++j) acc[i][j] = 0ull;

        const float* ebase = &sm.e[buf][0];
        #pragma unroll 4
        for (int d = 0; d < D_DIM; ++d) {
            unsigned long long za[8], eb[8];
            #pragma unroll
            for (int i = 0; i < 8; ++i)
                za[i] = *reinterpret_cast<const unsigned long long*>(&zrow[i * 65 + d]);
            #pragma unroll
            for (int j = 0; j < 8; ++j)
                eb[j] = *reinterpret_cast<const unsigned long long*>(
                            &ebase[d * CHUNK + j * 32 + tc * 2]);
            #pragma unroll
            for (int i = 0; i < 8; ++i)
                #pragma unroll
                for (int j = 0; j < 8; ++j)
                    asm("fma.rn.f32x2 %0, %1, %2, %0;"
                        : "+l"(acc[i][j]) : "l"(za[i]), "l"(eb[j]));
        }

        // dist = fl(fl(zz+ee) - dot), running strict-< argmin (first index wins)
        #pragma unroll
        for (int j = 0; j < 8; ++j) {
            const int code0 = c * CHUNK + j * 32 + tc * 2;
            float ee0 = sm.ee[buf][j * 32 + tc * 2];
            float ee1 = sm.ee[buf][j * 32 + tc * 2 + 1];
            #pragma unroll
            for (int i = 0; i < 8; ++i) {
                unsigned int lo, hi;
                asm("mov.b64 {%0, %1}, %2;" : "=r"(lo), "=r"(hi) : "l"(acc[i][j]));
                float d0 = __fsub_rn(__fadd_rn(rzz[i], ee0), __uint_as_float(lo));
                if (d0 < bestV[i]) { bestV[i] = d0; bestI[i] = code0; }
                float d1 = __fsub_rn(__fadd_rn(rzz[i], ee1), __uint_as_float(hi));
                if (d1 < bestV[i]) { bestV[i] = d1; bestI[i] = code0 + 1; }
            }
        }

        if (c + 1 < N_CHUNKS) asm volatile("cp.async.wait_group 0;" ::: "memory");
        __syncthreads();
    }

    // ---- cross-thread argmin reduce (lexicographic (val, idx)) ----
    #pragma unroll
    for (int i = 0; i < 8; ++i) {
        sm.redV[(tr * 8 + i) * 16 + tc] = bestV[i];
        sm.redI[(tr * 8 + i) * 16 + tc] = bestI[i];
    }
    __syncthreads();

    if (tid < ROWS_CTA) {
        const int row = tid;
        float v  = sm.redV[row * 16];
        int   bi = sm.redI[row * 16];
        #pragma unroll
        for (int t = 1; t < 16; ++t) {
            float vv = sm.redV[row * 16 + t];
            int   ii = sm.redI[row * 16 + t];
            if (vv < v || (vv == v && ii < bi)) { v = vv; bi = ii; }
        }
        const int gRow = rowBase + row;
        out[NQ_ELEMS + gRow] = (float)bi;          // indices as float32

        const float*  eRow = emb + (size_t)bi * D_DIM;
        const float2* zr   = &sm.zdup[row * 65];
        float* oRow = out + (size_t)gRow * D_DIM;
        double lpart = 0.0;
        for (int d = 0; d < D_DIM; ++d) {
            float q    = __ldg(&eRow[d]);
            float zv   = 0.5f * zr[d].x;
            float diff = __fsub_rn(q, zv);          // fl(q - z)
            oRow[d]    = __fadd_rn(zv, diff);       // quantized_st
            lpart += (double)__fmul_rn(diff, diff);
        }
        sm.lossBuf[row] = lpart;
    }
    __syncthreads();

    if (tid == 0) {
        double s = 0.0;
        for (int r = 0; r < ROWS_CTA; ++r) s += sm.lossBuf[r];  // fixed order
        g_lossPart[blockIdx.x] = s;
    }
}

// ---------------------------------------------------------------------------
// Finalize loss: deterministic serial reduction of per-CTA partials
// ---------------------------------------------------------------------------
__global__ void vq_finalize(float* __restrict__ out) {
    double s = 0.0;
    for (int i = 0; i < N_BLOCKS; ++i) s += g_lossPart[i];
    float m = (float)(s / (double)NQ_ELEMS);     // e_latent == q_latent numerically
    out[NQ_ELEMS + N_ROWS] = __fadd_rn(m, m);    // vq_loss = e + q
}

// ---------------------------------------------------------------------------
extern "C" void kernel_launch(void* const* d_in, const int* in_sizes, int n_in,
                              void* d_out, int out_size) {
    const float* z   = (const float*)d_in[0];   // [B,S,D] = 16*4096*64
    const float* emb = (const float*)d_in[1];   // [K,D]   = 4096*64
    float* out = (float*)d_out;                 // [quantized | indices | loss]

    static_assert(sizeof(Smem) <= 227 * 1024, "smem too big");
    cudaFuncSetAttribute(vq_main, cudaFuncAttributeMaxDynamicSharedMemorySize,
                         (int)sizeof(Smem));

    vq_prep<<<K_CODES / 256, 256>>>(emb);
    vq_main<<<N_BLOCKS, THREADS, sizeof(Smem)>>>(z, emb, out);
    vq_finalize<<<1, 1>>>(out);
}

// round 4
// speedup vs baseline: 1.1252x; 1.1252x over previous
#include <cuda_runtime.h>
#include <cstdint>

// Problem constants: B=16, S=4096, D=64, K=4096
#define D_DIM     64
#define K_CODES   4096
#define N_ROWS    65536               // B*S
#define ROWS_CTA  64
#define THREADS   128
#define CHUNK     128                 // codes per smem chunk
#define N_CHUNKS  (K_CODES / CHUNK)   // 32
#define N_BLOCKS  (N_ROWS / ROWS_CTA) // 1024
#define NQ_ELEMS  (N_ROWS * D_DIM)    // 4194304

// Device-global scratch (no allocations allowed)
__device__ float  g_embT[D_DIM * K_CODES];   // transposed codebook [d][k]
__device__ float  g_ee[K_CODES];             // ||e_k||^2, serial fp32
__device__ double g_lossPart[N_BLOCKS];      // per-CTA loss partials

__device__ __forceinline__ uint32_t smem_u32(const void* p) {
    return (uint32_t)__cvta_generic_to_shared(p);
}

#define CP16(dst, src) \
    asm volatile("cp.async.cg.shared.global [%0], [%1], 16;" :: "r"(dst), "l"(src))

struct __align__(16) Smem {
    float  e[2][D_DIM * CHUNK];   //  65536 B : embT chunk [d][c], double buffered
    float  ee[2][CHUNK];          //   1024 B
    float2 zdup[ROWS_CTA * 65];   //  33280 B : (2z,2z) per (row,d), stride 65
    float  zz[ROWS_CTA];          //    256 B
    float  redV[ROWS_CTA * 16];   //   4096 B
    int    redI[ROWS_CTA * 16];   //   4096 B
    double lossBuf[ROWS_CTA];     //    512 B
};                                // total 108800 B -> occupancy 2

// ---------------------------------------------------------------------------
// Prep: smem-tiled transpose (coalesced both sides) + ||e||^2 serial chain
// One block per 32 codebook rows.
// ---------------------------------------------------------------------------
__global__ void vq_prep(const float* __restrict__ emb) {
    __shared__ float tile[32][D_DIM + 1];    // [k_local][d], pad to kill conflicts
    const int tid = threadIdx.x;             // 256 threads
    const int k0  = blockIdx.x * 32;

    // load 32 rows x 64 d, coalesced over d
    #pragma unroll
    for (int it = 0; it < 8; ++it) {
        int i = tid + it * 256;              // 0..2047
        int kl = i >> 6, d = i & 63;
        tile[kl][d] = __ldg(&emb[(size_t)(k0 + kl) * D_DIM + d]);
    }
    __syncthreads();

    // store transposed, coalesced over k (32 consecutive k per row)
    #pragma unroll
    for (int it = 0; it < 8; ++it) {
        int i = tid + it * 256;              // 0..2047
        int d = i >> 5, kl = i & 31;
        g_embT[(size_t)d * K_CODES + k0 + kl] = tile[kl][d];
    }

    // ee: serial fl(s + fl(v*v)) over d, one thread per k
    if (tid < 32) {
        float s = 0.0f;
        #pragma unroll
        for (int d = 0; d < D_DIM; ++d) {
            float v = tile[tid][d];
            s = __fadd_rn(s, __fmul_rn(v, v));
        }
        g_ee[k0 + tid] = s;
    }
}

// ---------------------------------------------------------------------------
// Main kernel
// ---------------------------------------------------------------------------
__device__ __forceinline__ void load_chunk(Smem& sm, int buf, int chunk, int tid) {
    // chunk tile: 64 d-rows x 128 floats = 2048 x 16B segments (32 segs/row)
    uint32_t eBase = smem_u32(&sm.e[buf][0]);
    #pragma unroll
    for (int it = 0; it < 16; ++it) {
        int i   = tid + it * THREADS;        // 0..2047
        int d   = i >> 5;                    // 0..63
        int seg = i & 31;                    // 0..31
        uint32_t dst = eBase + (uint32_t)(d * CHUNK + seg * 4) * 4u;
        const float* s = g_embT + (size_t)d * K_CODES + chunk * CHUNK + seg * 4;
        CP16(dst, s);
    }
    if (tid < 32) {
        uint32_t dst = smem_u32(&sm.ee[buf][0]) + tid * 16;
        const float* s = g_ee + chunk * CHUNK + tid * 4;
        CP16(dst, s);
    }
    asm volatile("cp.async.commit_group;" ::: "memory");
}

__global__ void __launch_bounds__(THREADS, 2)
vq_main(const float* __restrict__ z, const float* __restrict__ emb,
        float* __restrict__ out)
{
    extern __shared__ unsigned char smraw[];
    Smem& sm = *reinterpret_cast<Smem*>(smraw);

    const int tid = threadIdx.x;
    const int tc  = tid & 15;     // code lane 0..15
    const int tr  = tid >> 4;     // row group 0..7 (8 rows each)
    const int rowBase = blockIdx.x * ROWS_CTA;

    // ---- load z tile, store duplicated (2z,2z); 2z exact ----
    const float4* zg = reinterpret_cast<const float4*>(z + (size_t)rowBase * D_DIM);
    #pragma unroll
    for (int it = 0; it < 8; ++it) {
        int q = tid + it * THREADS;          // 0..1023 float4s
        float4 v = zg[q];
        int row = q >> 4;
        int c   = (q & 15) << 2;
        float2* p = &sm.zdup[row * 65 + c];
        p[0] = make_float2(v.x + v.x, v.x + v.x);
        p[1] = make_float2(v.y + v.y, v.y + v.y);
        p[2] = make_float2(v.z + v.z, v.z + v.z);
        p[3] = make_float2(v.w + v.w, v.w + v.w);
    }
    __syncthreads();

    // ---- zz per row: serial fl(s + fl(z*z)) ----
    if (tid < ROWS_CTA) {
        float s = 0.0f;
        const float2* zr = &sm.zdup[tid * 65];
        #pragma unroll
        for (int d = 0; d < D_DIM; ++d) {
            float zv = 0.5f * zr[d].x;       // exact recovery of z
            s = __fadd_rn(s, __fmul_rn(zv, zv));
        }
        sm.zz[tid] = s;
    }
    __syncthreads();

    float rzz[8];
    #pragma unroll
    for (int i = 0; i < 8; ++i) rzz[i] = sm.zz[tr * 8 + i];

    float bestV[8];
    int   bestI[8];
    #pragma unroll
    for (int i = 0; i < 8; ++i) { bestV[i] = 3.402823466e38f; bestI[i] = 0; }

    load_chunk(sm, 0, 0, tid);
    asm volatile("cp.async.wait_group 0;" ::: "memory");
    __syncthreads();

    const float2* zrow = &sm.zdup[tr * 8 * 65];

    for (int c = 0; c < N_CHUNKS; ++c) {
        const int buf = c & 1;
        if (c + 1 < N_CHUNKS) load_chunk(sm, (c + 1) & 1, c + 1, tid);

        // acc[i][j] = serial fma chain over d of (2z)*e, packed f32x2
        unsigned long long acc[8][4];
        #pragma unroll
        for (int i = 0; i < 8; ++i)
            #pragma unroll
            for (int j = 0; j < 4; ++j) acc[i][j] = 0ull;

        const float* ebase = &sm.e[buf][0];
        #pragma unroll 4
        for (int d = 0; d < D_DIM; ++d) {
            unsigned long long za[8], eb[4];
            #pragma unroll
            for (int i = 0; i < 8; ++i)
                za[i] = *reinterpret_cast<const unsigned long long*>(&zrow[i * 65 + d]);
            #pragma unroll
            for (int j = 0; j < 4; ++j)
                eb[j] = *reinterpret_cast<const unsigned long long*>(
                            &ebase[d * CHUNK + j * 32 + tc * 2]);
            #pragma unroll
            for (int i = 0; i < 8; ++i)
                #pragma unroll
                for (int j = 0; j < 4; ++j)
                    asm("fma.rn.f32x2 %0, %1, %2, %0;"
                        : "+l"(acc[i][j]) : "l"(za[i]), "l"(eb[j]));
        }

        // dist = fl(fl(zz+ee) - dot), running strict-< argmin (first index wins)
        #pragma unroll
        for (int j = 0; j < 4; ++j) {
            const int code0 = c * CHUNK + j * 32 + tc * 2;
            float ee0 = sm.ee[buf][j * 32 + tc * 2];
            float ee1 = sm.ee[buf][j * 32 + tc * 2 + 1];
            #pragma unroll
            for (int i = 0; i < 8; ++i) {
                unsigned int lo, hi;
                asm("mov.b64 {%0, %1}, %2;" : "=r"(lo), "=r"(hi) : "l"(acc[i][j]));
                float d0 = __fsub_rn(__fadd_rn(rzz[i], ee0), __uint_as_float(lo));
                if (d0 < bestV[i]) { bestV[i] = d0; bestI[i] = code0; }
                float d1 = __fsub_rn(__fadd_rn(rzz[i], ee1), __uint_as_float(hi));
                if (d1 < bestV[i]) { bestV[i] = d1; bestI[i] = code0 + 1; }
            }
        }

        if (c + 1 < N_CHUNKS) asm volatile("cp.async.wait_group 0;" ::: "memory");
        __syncthreads();
    }

    // ---- cross-thread argmin reduce (lexicographic (val, idx)) ----
    #pragma unroll
    for (int i = 0; i < 8; ++i) {
        sm.redV[(tr * 8 + i) * 16 + tc] = bestV[i];
        sm.redI[(tr * 8 + i) * 16 + tc] = bestI[i];
    }
    __syncthreads();

    if (tid < ROWS_CTA) {
        const int row = tid;
        float v  = sm.redV[row * 16];
        int   bi = sm.redI[row * 16];
        #pragma unroll
        for (int t = 1; t < 16; ++t) {
            float vv = sm.redV[row * 16 + t];
            int   ii = sm.redI[row * 16 + t];
            if (vv < v || (vv == v && ii < bi)) { v = vv; bi = ii; }
        }
        const int gRow = rowBase + row;
        out[NQ_ELEMS + gRow] = (float)bi;          // indices as float32

        const float*  eRow = emb + (size_t)bi * D_DIM;
        const float2* zr   = &sm.zdup[row * 65];
        float* oRow = out + (size_t)gRow * D_DIM;
        double lpart = 0.0;
        #pragma unroll
        for (int d = 0; d < D_DIM; ++d) {
            float q    = __ldg(&eRow[d]);
            float zv   = 0.5f * zr[d].x;
            float diff = __fsub_rn(q, zv);          // fl(q - z)
            oRow[d]    = __fadd_rn(zv, diff);       // quantized_st
            lpart += (double)__fmul_rn(diff, diff);
        }
        sm.lossBuf[row] = lpart;
    }
    __syncthreads();

    if (tid == 0) {
        double s = 0.0;
        #pragma unroll
        for (int r = 0; r < ROWS_CTA; ++r) s += sm.lossBuf[r];  // fixed order
        g_lossPart[blockIdx.x] = s;
    }
}

// ---------------------------------------------------------------------------
// Finalize loss: deterministic tree reduction of per-CTA partials
// ---------------------------------------------------------------------------
__global__ void vq_finalize(float* __restrict__ out) {
    __shared__ double red[128];
    const int tid = threadIdx.x;                 // 128 threads
    double s = 0.0;
    #pragma unroll
    for (int i = 0; i < N_BLOCKS / 128; ++i)     // 8 each, fixed order
        s += g_lossPart[tid * (N_BLOCKS / 128) + i];
    red[tid] = s;
    __syncthreads();
    #pragma unroll
    for (int off = 64; off > 0; off >>= 1) {
        if (tid < off) red[tid] += red[tid + off];
        __syncthreads();
    }
    if (tid == 0) {
        float m = (float)(red[0] / (double)NQ_ELEMS);
        out[NQ_ELEMS + N_ROWS] = __fadd_rn(m, m);    // vq_loss = e + q
    }
}

// ---------------------------------------------------------------------------
extern "C" void kernel_launch(void* const* d_in, const int* in_sizes, int n_in,
                              void* d_out, int out_size) {
    const float* z   = (const float*)d_in[0];   // [B,S,D] = 16*4096*64
    const float* emb = (const float*)d_in[1];   // [K,D]   = 4096*64
    float* out = (float*)d_out;                 // [quantized | indices | loss]

    static_assert(sizeof(Smem) <= 113 * 1024, "smem too big for occ 2");
    cudaFuncSetAttribute(vq_main, cudaFuncAttributeMaxDynamicSharedMemorySize,
                         (int)sizeof(Smem));

    vq_prep<<<K_CODES / 32, 256>>>(emb);
    vq_main<<<N_BLOCKS, THREADS, sizeof(Smem)>>>(z, emb, out);
    vq_finalize<<<1, 128>>>(out);
}